// round 9
// baseline (speedup 1.0000x reference)
#include <cuda_runtime.h>
#include <cuda_fp16.h>

#define HIDDEN 128
#define NNODES 50000
#define NEDGES 640000
#define NBUCKETS 782            // ceil(50000/64): bucket = src >> 6

// Scratch (allocation-free rule: device globals)
__device__ __align__(16) __half g_ABh[NNODES * 256]; // per node: [A+bias1 (128) | B (128)], fp16
__device__ __align__(16) uint2  g_se[NEDGES];        // sorted: {src<<16|dst, e}
__device__ int g_hist[NBUCKETS];
__device__ int g_cur[NBUCKETS];

// ---------------------------------------------------------------------------
__device__ __forceinline__ int detect_is64_block(const int* ei) {
    __shared__ int s_is64;
    if (threadIdx.x < 32) {
        unsigned m = __ballot_sync(0xffffffffu, ei[2 * threadIdx.x + 1] != 0);
        if (threadIdx.x == 0) s_is64 = (m == 0) ? 1 : 0;
    }
    __syncthreads();
    return s_is64;
}

__device__ __forceinline__ void load_edge(const int* ei, int is64, int e,
                                          int& src, int& dst) {
    if (is64) {
        const long long* e64 = (const long long*)ei;
        src = (int)__ldg(e64 + e);
        dst = (int)__ldg(e64 + NEDGES + e);
    } else {
        src = __ldg(ei + e);
        dst = __ldg(ei + NEDGES + e);
    }
}

// ---------------------------------------------------------------------------
// Histogram of src buckets. 625 blocks x 1024 edges.
__global__ __launch_bounds__(256) void hist_kernel(const int* __restrict__ ei) {
    __shared__ int sh[NBUCKETS];
    const int is64 = detect_is64_block(ei);
    for (int i = threadIdx.x; i < NBUCKETS; i += 256) sh[i] = 0;
    __syncthreads();
    int base = blockIdx.x * 1024;
    #pragma unroll
    for (int i = 0; i < 4; i++) {
        int e = base + i * 256 + threadIdx.x;
        if (e < NEDGES) {
            int src;
            if (is64) src = (int)__ldg((const long long*)ei + e);
            else      src = __ldg(ei + e);
            atomicAdd(&sh[src >> 6], 1);
        }
    }
    __syncthreads();
    for (int i = threadIdx.x; i < NBUCKETS; i += 256) {
        int c = sh[i];
        if (c) atomicAdd(&g_hist[i], c);
    }
}

// Exclusive scan of 782 bucket counts -> g_cur. Single block, 256 threads x 4.
__global__ __launch_bounds__(256) void scan_kernel() {
    __shared__ int ssum[256];
    int t = threadIdx.x;
    int v[4], s = 0;
    #pragma unroll
    for (int i = 0; i < 4; i++) {
        int b = t * 4 + i;
        v[i] = (b < NBUCKETS) ? g_hist[b] : 0;
        s += v[i];
    }
    ssum[t] = s;
    __syncthreads();
    #pragma unroll
    for (int off = 1; off < 256; off <<= 1) {
        int x = ssum[t];
        int y = (t >= off) ? ssum[t - off] : 0;
        __syncthreads();
        ssum[t] = x + y;
        __syncthreads();
    }
    int run = (t == 0) ? 0 : ssum[t - 1];
    #pragma unroll
    for (int i = 0; i < 4; i++) {
        int b = t * 4 + i;
        if (b < NBUCKETS) { g_cur[b] = run; run += v[i]; }
    }
}

// Scatter edges into bucket-sorted order (packed {src<<16|dst, e}).
__global__ __launch_bounds__(256) void scatter_kernel(const int* __restrict__ ei) {
    const int is64 = detect_is64_block(ei);
    int e = blockIdx.x * 256 + threadIdx.x;
    if (e >= NEDGES) return;
    int src, dst;
    load_edge(ei, is64, e, src, dst);
    int p = atomicAdd(&g_cur[src >> 6], 1);
    g_se[p] = make_uint2(((unsigned)src << 16) | (unsigned)dst, (unsigned)e);
}

// ---------------------------------------------------------------------------
// Tensor-core GEMM with inline Z convert AND inline W1 pack (unchanged R6 design).
#define AS_ROW 136
#define BS_ROW 136
#define GEMM_SMEM ((64 * AS_ROW + 256 * BS_ROW) * 2)   // 87040 bytes

__device__ __forceinline__ void mma16816(float* d, unsigned a0, unsigned a1,
                                         unsigned a2, unsigned a3,
                                         unsigned b0, unsigned b1) {
    asm volatile(
        "mma.sync.aligned.m16n8k16.row.col.f32.f16.f16.f32 "
        "{%0,%1,%2,%3}, {%4,%5,%6,%7}, {%8,%9}, {%0,%1,%2,%3};"
        : "+f"(d[0]), "+f"(d[1]), "+f"(d[2]), "+f"(d[3])
        : "r"(a0), "r"(a1), "r"(a2), "r"(a3), "r"(b0), "r"(b1));
}

__global__ __launch_bounds__(256, 2) void gemm_kernel(const float* __restrict__ Z,
                                                      const float* __restrict__ W1,
                                                      const float* __restrict__ bias1) {
    extern __shared__ __half sm[];
    __half* As = sm;                   // [64][AS_ROW]
    __half* Bs = sm + 64 * AS_ROW;     // [256][BS_ROW]

    const int tid = threadIdx.x;
    const int m0 = blockIdx.x * 64;

    float4 va[8];
    #pragma unroll
    for (int i = 0; i < 8; i++) {
        int ch = tid + i * 256;
        int row = ch >> 5, c4 = ch & 31;
        int gr = m0 + row;
        if (gr < NNODES) va[i] = *(const float4*)(Z + (size_t)gr * HIDDEN + c4 * 4);
        else             va[i] = make_float4(0.f, 0.f, 0.f, 0.f);
    }

    #pragma unroll
    for (int bt = 0; bt < 4; bt++) {
        float4 vb[8];
        #pragma unroll
        for (int i = 0; i < 8; i++) {
            int ch = tid + (bt * 8 + i) * 256;
            vb[i] = *(const float4*)(W1 + (size_t)ch * 4);
        }
        #pragma unroll
        for (int i = 0; i < 8; i++) {
            int ch = tid + (bt * 8 + i) * 256;
            int s = ch >> 5, c4 = ch & 31;
            int n = (s & 1) ? 128 + (s >> 1) : (s >> 1);
            __half2* d2 = (__half2*)(Bs + n * BS_ROW + c4 * 4);
            d2[0] = __floats2half2_rn(vb[i].x, vb[i].y);
            d2[1] = __floats2half2_rn(vb[i].z, vb[i].w);
        }
    }

    #pragma unroll
    for (int i = 0; i < 8; i++) {
        int ch = tid + i * 256;
        int row = ch >> 5, c4 = ch & 31;
        __half2* d2 = (__half2*)(As + row * AS_ROW + c4 * 4);
        d2[0] = __floats2half2_rn(va[i].x, va[i].y);
        d2[1] = __floats2half2_rn(va[i].z, va[i].w);
    }
    __syncthreads();

    const int wid = tid >> 5;
    const int lane = tid & 31;
    const int mbase = (wid >> 2) * 32;
    const int nbase = (wid & 3) * 64;
    const int g = lane >> 2;
    const int tq = lane & 3;
    const int row_l = lane & 15;
    const int a_hi = (lane >> 4) << 3;
    const int b_row = lane & 7;
    const int b_koff = ((lane >> 3) & 1) * 8;

    float acc[2][8][4];
    #pragma unroll
    for (int mi = 0; mi < 2; mi++)
        #pragma unroll
        for (int ni = 0; ni < 8; ni++)
            #pragma unroll
            for (int c = 0; c < 4; c++) acc[mi][ni][c] = 0.f;

    #pragma unroll
    for (int kc = 0; kc < 8; kc++) {
        unsigned a[2][4];
        #pragma unroll
        for (int mi = 0; mi < 2; mi++) {
            const __half* p = As + (mbase + mi * 16 + row_l) * AS_ROW + kc * 16 + a_hi;
            unsigned sa = (unsigned)__cvta_generic_to_shared(p);
            asm volatile("ldmatrix.sync.aligned.m8n8.x4.shared.b16 {%0,%1,%2,%3}, [%4];"
                         : "=r"(a[mi][0]), "=r"(a[mi][1]), "=r"(a[mi][2]), "=r"(a[mi][3])
                         : "r"(sa));
        }
        unsigned bf[8][2];
        #pragma unroll
        for (int ni = 0; ni < 8; ni++) {
            const __half* p = Bs + (nbase + ni * 8 + b_row) * BS_ROW + kc * 16 + b_koff;
            unsigned sb = (unsigned)__cvta_generic_to_shared(p);
            asm volatile("ldmatrix.sync.aligned.m8n8.x2.shared.b16 {%0,%1}, [%2];"
                         : "=r"(bf[ni][0]), "=r"(bf[ni][1])
                         : "r"(sb));
        }
        #pragma unroll
        for (int mi = 0; mi < 2; mi++)
            #pragma unroll
            for (int ni = 0; ni < 8; ni++)
                mma16816(acc[mi][ni], a[mi][0], a[mi][1], a[mi][2], a[mi][3],
                         bf[ni][0], bf[ni][1]);
    }

    #pragma unroll
    for (int ni = 0; ni < 8; ni++) {
        int ncol = nbase + ni * 8 + tq * 2;
        float bx = 0.f, by = 0.f;
        if (ncol < 128) { bx = bias1[ncol]; by = bias1[ncol + 1]; }
        #pragma unroll
        for (int mi = 0; mi < 2; mi++) {
            int r0 = m0 + mbase + mi * 16 + g;
            if (r0 < NNODES) {
                *(__half2*)(g_ABh + (size_t)r0 * 256 + ncol) =
                    __floats2half2_rn(acc[mi][ni][0] + bx, acc[mi][ni][1] + by);
            }
            int r1 = r0 + 8;
            if (r1 < NNODES) {
                *(__half2*)(g_ABh + (size_t)r1 * 256 + ncol) =
                    __floats2half2_rn(acc[mi][ni][2] + bx, acc[mi][ni][3] + by);
            }
        }
    }
}

// ---------------------------------------------------------------------------
// Per-edge pass over SORTED edges: contiguous runs share src buckets so A-half
// gathers hit L1. 16 lanes/edge, 2 edges per warp, 34 edges per warp chunk.
#define EPW 34                       // edges per warp (contiguous)
#define BLK_E (8 * EPW)              // 272 edges per block
#define EDGE_BLOCKS ((NEDGES + BLK_E - 1) / BLK_E)

__global__ __launch_bounds__(256) void edge_kernel(
    const float* __restrict__ W2,
    const float* __restrict__ bias2,
    float* __restrict__ out)
{
    const int lane = threadIdx.x & 31;
    const int sl = lane & 15;
    const int sub = lane >> 4;
    const int w = threadIdx.x >> 5;
    const int base0 = blockIdx.x * BLK_E + w * EPW;

    const float4 w2a = *(const float4*)(W2 + sl * 8);
    const float4 w2b = *(const float4*)(W2 + sl * 8 + 4);
    const float b2 = bias2[0];
    const __half2 zero2 = __float2half2_rn(0.f);

    #pragma unroll 2
    for (int i = 0; i < EPW / 2; i++) {
        int ep = base0 + 2 * i + sub;
        if (ep >= NEDGES) break;
        uint2 se = __ldg(&g_se[ep]);
        int src = se.x >> 16;
        int dst = se.x & 0xffff;

        uint4 av = *(const uint4*)(g_ABh + (size_t)src * 256 + sl * 8);
        uint4 bv = *(const uint4*)(g_ABh + (size_t)dst * 256 + 128 + sl * 8);
        const __half2* ah = (const __half2*)&av;
        const __half2* bh = (const __half2*)&bv;

        float2 f0 = __half22float2(__hmax2(__hadd2(ah[0], bh[0]), zero2));
        float2 f1 = __half22float2(__hmax2(__hadd2(ah[1], bh[1]), zero2));
        float2 f2 = __half22float2(__hmax2(__hadd2(ah[2], bh[2]), zero2));
        float2 f3 = __half22float2(__hmax2(__hadd2(ah[3], bh[3]), zero2));

        float acc = w2a.x * f0.x + w2a.y * f0.y + w2a.z * f1.x + w2a.w * f1.y
                  + w2b.x * f2.x + w2b.y * f2.y + w2b.z * f3.x + w2b.w * f3.y;

        acc += __shfl_xor_sync(0xffffffffu, acc, 1);
        acc += __shfl_xor_sync(0xffffffffu, acc, 2);
        acc += __shfl_xor_sync(0xffffffffu, acc, 4);
        acc += __shfl_xor_sync(0xffffffffu, acc, 8);

        if (sl == 0) out[se.y] = acc + b2;
    }
}

// ---------------------------------------------------------------------------
extern "C" void kernel_launch(void* const* d_in, const int* in_sizes, int n_in,
                              void* d_out, int out_size) {
    const float* z     = (const float*)d_in[0];   // [50000,128]
    const float* W1    = (const float*)d_in[1];   // [128,256]
    const float* bias1 = (const float*)d_in[2];   // [128]
    const float* W2    = (const float*)d_in[3];   // [1,128]
    const float* bias2 = (const float*)d_in[4];   // [1]
    const int*   ei    = (const int*)d_in[5];     // [2,640000]
    float* out = (float*)d_out;

    static void* hist_ptr = nullptr;
    static int smem_set = 0;
    if (!smem_set) {
        cudaFuncSetAttribute(gemm_kernel,
                             cudaFuncAttributeMaxDynamicSharedMemorySize, GEMM_SMEM);
        cudaGetSymbolAddress(&hist_ptr, g_hist);
        smem_set = 1;
    }

    cudaMemsetAsync(hist_ptr, 0, NBUCKETS * sizeof(int));
    hist_kernel<<<(NEDGES + 1023) / 1024, 256>>>(ei);
    scan_kernel<<<1, 256>>>();
    scatter_kernel<<<(NEDGES + 255) / 256, 256>>>(ei);

    gemm_kernel<<<(NNODES + 63) / 64, 256, GEMM_SMEM>>>(z, W1, bias1);

    edge_kernel<<<EDGE_BLOCKS, 256>>>(W2, bias2, out);
}

// round 10
// speedup vs baseline: 2.1227x; 2.1227x over previous
#include <cuda_runtime.h>
#include <cuda_fp16.h>

#define HIDDEN 128
#define NNODES 50000
#define NEDGES 640000

// Scratch (allocation-free rule: device globals)
__device__ __align__(16) __half g_ABh[NNODES * 256];  // per node: [A+bias1 (128) | B (128)], fp16

// ---------------------------------------------------------------------------
// Tensor-core GEMM with inline Z convert AND inline W1 pack (R6 design).
// AB = fp16(Z) @ fp16(W1 split). Block 64M x 256N, K=128 fully resident.
// 8 warps (2m x 4n), warp tile 32x64.
#define AS_ROW 136   // halves per A smem row: 128 data + 8 pad
#define BS_ROW 136   // halves per B smem row: 128 data + 8 pad
#define GEMM_SMEM ((64 * AS_ROW + 256 * BS_ROW) * 2)   // 87040 bytes

__device__ __forceinline__ void mma16816(float* d, unsigned a0, unsigned a1,
                                         unsigned a2, unsigned a3,
                                         unsigned b0, unsigned b1) {
    asm volatile(
        "mma.sync.aligned.m16n8k16.row.col.f32.f16.f16.f32 "
        "{%0,%1,%2,%3}, {%4,%5,%6,%7}, {%8,%9}, {%0,%1,%2,%3};"
        : "+f"(d[0]), "+f"(d[1]), "+f"(d[2]), "+f"(d[3])
        : "r"(a0), "r"(a1), "r"(a2), "r"(a3), "r"(b0), "r"(b1));
}

__global__ __launch_bounds__(256, 2) void gemm_kernel(const float* __restrict__ Z,
                                                      const float* __restrict__ W1,
                                                      const float* __restrict__ bias1) {
    extern __shared__ __half sm[];
    __half* As = sm;                   // [64][AS_ROW]
    __half* Bs = sm + 64 * AS_ROW;     // [256][BS_ROW]

    const int tid = threadIdx.x;
    const int m0 = blockIdx.x * 64;

    // ---- A tile LDG first (DRAM latency): 64 rows x 32 float4; 8/thread ----
    float4 va[8];
    #pragma unroll
    for (int i = 0; i < 8; i++) {
        int ch = tid + i * 256;
        int row = ch >> 5, c4 = ch & 31;
        int gr = m0 + row;
        if (gr < NNODES) va[i] = *(const float4*)(Z + (size_t)gr * HIDDEN + c4 * 4);
        else             va[i] = make_float4(0.f, 0.f, 0.f, 0.f);
    }

    // ---- B tile: W1 fp32 (L2-hot) -> cvt -> STS with row permutation ----
    // W1 flat [256][128]: src row 2j -> Bs row j (A-half), 2j+1 -> 128+j (B-half)
    #pragma unroll
    for (int bt = 0; bt < 4; bt++) {
        float4 vb[8];
        #pragma unroll
        for (int i = 0; i < 8; i++) {
            int ch = tid + (bt * 8 + i) * 256;
            vb[i] = *(const float4*)(W1 + (size_t)ch * 4);
        }
        #pragma unroll
        for (int i = 0; i < 8; i++) {
            int ch = tid + (bt * 8 + i) * 256;
            int s = ch >> 5, c4 = ch & 31;
            int n = (s & 1) ? 128 + (s >> 1) : (s >> 1);
            __half2* d2 = (__half2*)(Bs + n * BS_ROW + c4 * 4);
            d2[0] = __floats2half2_rn(vb[i].x, vb[i].y);
            d2[1] = __floats2half2_rn(vb[i].z, vb[i].w);
        }
    }

    // ---- A cvt + STS ----
    #pragma unroll
    for (int i = 0; i < 8; i++) {
        int ch = tid + i * 256;
        int row = ch >> 5, c4 = ch & 31;
        __half2* d2 = (__half2*)(As + row * AS_ROW + c4 * 4);
        d2[0] = __floats2half2_rn(va[i].x, va[i].y);
        d2[1] = __floats2half2_rn(va[i].z, va[i].w);
    }
    __syncthreads();

    const int wid = tid >> 5;
    const int lane = tid & 31;
    const int mbase = (wid >> 2) * 32;
    const int nbase = (wid & 3) * 64;
    const int g = lane >> 2;
    const int tq = lane & 3;
    const int row_l = lane & 15;
    const int a_hi = (lane >> 4) << 3;
    const int b_row = lane & 7;
    const int b_koff = ((lane >> 3) & 1) * 8;

    float acc[2][8][4];
    #pragma unroll
    for (int mi = 0; mi < 2; mi++)
        #pragma unroll
        for (int ni = 0; ni < 8; ni++)
            #pragma unroll
            for (int c = 0; c < 4; c++) acc[mi][ni][c] = 0.f;

    #pragma unroll
    for (int kc = 0; kc < 8; kc++) {
        unsigned a[2][4];
        #pragma unroll
        for (int mi = 0; mi < 2; mi++) {
            const __half* p = As + (mbase + mi * 16 + row_l) * AS_ROW + kc * 16 + a_hi;
            unsigned sa = (unsigned)__cvta_generic_to_shared(p);
            asm volatile("ldmatrix.sync.aligned.m8n8.x4.shared.b16 {%0,%1,%2,%3}, [%4];"
                         : "=r"(a[mi][0]), "=r"(a[mi][1]), "=r"(a[mi][2]), "=r"(a[mi][3])
                         : "r"(sa));
        }
        unsigned bf[8][2];
        #pragma unroll
        for (int ni = 0; ni < 8; ni++) {
            const __half* p = Bs + (nbase + ni * 8 + b_row) * BS_ROW + kc * 16 + b_koff;
            unsigned sb = (unsigned)__cvta_generic_to_shared(p);
            asm volatile("ldmatrix.sync.aligned.m8n8.x2.shared.b16 {%0,%1}, [%2];"
                         : "=r"(bf[ni][0]), "=r"(bf[ni][1])
                         : "r"(sb));
        }
        #pragma unroll
        for (int mi = 0; mi < 2; mi++)
            #pragma unroll
            for (int ni = 0; ni < 8; ni++)
                mma16816(acc[mi][ni], a[mi][0], a[mi][1], a[mi][2], a[mi][3],
                         bf[ni][0], bf[ni][1]);
    }

    // ---- epilogue: +bias1 on cols <128, fp16 store to g_ABh ----
    #pragma unroll
    for (int ni = 0; ni < 8; ni++) {
        int ncol = nbase + ni * 8 + tq * 2;
        float bx = 0.f, by = 0.f;
        if (ncol < 128) { bx = bias1[ncol]; by = bias1[ncol + 1]; }
        #pragma unroll
        for (int mi = 0; mi < 2; mi++) {
            int r0 = m0 + mbase + mi * 16 + g;
            if (r0 < NNODES) {
                *(__half2*)(g_ABh + (size_t)r0 * 256 + ncol) =
                    __floats2half2_rn(acc[mi][ni][0] + bx, acc[mi][ni][1] + by);
            }
            int r1 = r0 + 8;
            if (r1 < NNODES) {
                *(__half2*)(g_ABh + (size_t)r1 * 256 + ncol) =
                    __floats2half2_rn(acc[mi][ni][2] + bx, acc[mi][ni][3] + by);
            }
        }
    }
}

// ---------------------------------------------------------------------------
// Per-edge pass: 8 lanes per edge, 4 edges per warp (fewer shfl/index ops,
// deeper per-lane MLP: 4 independent uint4 gathers in flight).
// out[e] = bias2 + sum_j W2[j]*relu(A'[src][j]+B[dst][j])   (bias1 folded in A')
__global__ __launch_bounds__(256) void edge_kernel(
    const int* __restrict__ ei,
    const float* __restrict__ W2,
    const float* __restrict__ bias2,
    float* __restrict__ out)
{
    __shared__ int s_is64;
    if (threadIdx.x < 32) {
        unsigned m = __ballot_sync(0xffffffffu, ei[2 * threadIdx.x + 1] != 0);
        if (threadIdx.x == 0) s_is64 = (m == 0) ? 1 : 0;
    }

    const int lane = threadIdx.x & 31;
    const int sl = lane & 7;           // lane within edge-group (0..7)
    const int sub = lane >> 3;         // edge slot within warp (0..3)
    const int w = (blockIdx.x * blockDim.x + threadIdx.x) >> 5;
    const int nw = (gridDim.x * blockDim.x) >> 5;

    // 16 W2 coefficients per lane
    float4 w2c[4];
    #pragma unroll
    for (int i = 0; i < 4; i++) w2c[i] = *(const float4*)(W2 + sl * 16 + i * 4);
    const float b2 = bias2[0];
    const __half2 zero2 = __float2half2_rn(0.f);
    const long long* ei64 = (const long long*)ei;

    __syncthreads();
    const int is64 = s_is64;

    for (int base = 4 * w; base < NEDGES; base += 4 * nw) {
        const int e = base + sub;
        int src, dst;
        if (is64) {
            src = (int)__ldg(ei64 + e);
            dst = (int)__ldg(ei64 + NEDGES + e);
        } else {
            src = __ldg(ei + e);
            dst = __ldg(ei + NEDGES + e);
        }
        const __half* ap = g_ABh + (size_t)src * 256 + sl * 16;
        const __half* bp = g_ABh + (size_t)dst * 256 + 128 + sl * 16;
        uint4 av0 = *(const uint4*)(ap);
        uint4 av1 = *(const uint4*)(ap + 8);
        uint4 bv0 = *(const uint4*)(bp);
        uint4 bv1 = *(const uint4*)(bp + 8);

        const __half2* a0 = (const __half2*)&av0;
        const __half2* a1 = (const __half2*)&av1;
        const __half2* b0 = (const __half2*)&bv0;
        const __half2* b1 = (const __half2*)&bv1;

        float acc = 0.f;
        #pragma unroll
        for (int i = 0; i < 4; i++) {
            float2 f = __half22float2(__hmax2(__hadd2(a0[i], b0[i]), zero2));
            acc = fmaf(((const float*)&w2c[0])[2 * i],     f.x, acc);
            acc = fmaf(((const float*)&w2c[0])[2 * i + 1], f.y, acc);
        }
        #pragma unroll
        for (int i = 0; i < 4; i++) {
            float2 f = __half22float2(__hmax2(__hadd2(a1[i], b1[i]), zero2));
            acc = fmaf(((const float*)&w2c[2])[2 * i],     f.x, acc);
            acc = fmaf(((const float*)&w2c[2])[2 * i + 1], f.y, acc);
        }

        acc += __shfl_xor_sync(0xffffffffu, acc, 1);
        acc += __shfl_xor_sync(0xffffffffu, acc, 2);
        acc += __shfl_xor_sync(0xffffffffu, acc, 4);

        if (sl == 0) out[e] = acc + b2;
    }
}

// ---------------------------------------------------------------------------
extern "C" void kernel_launch(void* const* d_in, const int* in_sizes, int n_in,
                              void* d_out, int out_size) {
    const float* z     = (const float*)d_in[0];   // [50000,128]
    const float* W1    = (const float*)d_in[1];   // [128,256]
    const float* bias1 = (const float*)d_in[2];   // [128]
    const float* W2    = (const float*)d_in[3];   // [1,128]
    const float* bias2 = (const float*)d_in[4];   // [1]
    const int*   ei    = (const int*)d_in[5];     // [2,640000]
    float* out = (float*)d_out;

    static int smem_set = 0;
    if (!smem_set) {
        cudaFuncSetAttribute(gemm_kernel,
                             cudaFuncAttributeMaxDynamicSharedMemorySize, GEMM_SMEM);
        smem_set = 1;
    }

    gemm_kernel<<<(NNODES + 63) / 64, 256, GEMM_SMEM>>>(z, W1, bias1);

    edge_kernel<<<2368, 256>>>(ei, W2, bias2, out);
}